// round 3
// baseline (speedup 1.0000x reference)
#include <cuda_runtime.h>
#include <math_constants.h>

#define BB 4
#define VV 4096
#define FF 64
#define SS 4
#define KN 39            // neighbours kept (K_NEIGHBOURS=40 includes self)
#define OUTF 64
#define TPB 128
#define BND_MAX 64

// Scratch (device globals; no allocation allowed)
__device__ float g_coords[BB * VV * 4];     // (b, v, 4) — float4-aligned rows
__device__ float g_feats[BB * VV * FF];     // (b, v, 64)

// ---------------------------------------------------------------------------
// Kernel 1: coords = x@Ws + bs, feats = x@Wf + bf
// ---------------------------------------------------------------------------
__global__ void __launch_bounds__(64) prep_kernel(
    const float* __restrict__ x,
    const float* __restrict__ Wf, const float* __restrict__ bf,
    const float* __restrict__ Ws, const float* __restrict__ bs)
{
    const int vtx = blockIdx.x;        // 0 .. B*V-1
    const int f   = threadIdx.x;       // 0 .. 63
    __shared__ float sx[FF];
    sx[f] = x[vtx * FF + f];
    __syncthreads();

    float acc = bf[f];
#pragma unroll
    for (int k = 0; k < FF; ++k)
        acc = fmaf(sx[k], Wf[k * FF + f], acc);
    g_feats[vtx * FF + f] = acc;

    if (f < SS) {
        float c = bs[f];
#pragma unroll
        for (int k = 0; k < FF; ++k)
            c = fmaf(sx[k], Ws[k * SS + f], c);
        g_coords[vtx * 4 + f] = c;
    }
}

// ---------------------------------------------------------------------------
// Parallel "find first bin where cumulative count >= need" over 256 bins.
// 128 threads, 2 bins each. Writes (bin, count_before_bin) via out pointers.
// Exactly one thread satisfies the crossing condition.
// ---------------------------------------------------------------------------
__device__ __forceinline__ void scan_select_256(
    const unsigned* __restrict__ s_hist, int need, int tid,
    int* s_out_bin, int* s_out_c)
{
    __shared__ int s_wt[4];
    int h0 = (int)s_hist[2 * tid];
    int h1 = (int)s_hist[2 * tid + 1];
    int pair = h0 + h1;
    int incl = pair;
#pragma unroll
    for (int o = 1; o < 32; o <<= 1) {
        int n = __shfl_up_sync(0xffffffffu, incl, o);
        if ((tid & 31) >= o) incl += n;
    }
    if ((tid & 31) == 31) s_wt[tid >> 5] = incl;
    __syncthreads();
    int wprefix = 0;
    const int wid = tid >> 5;
    if (wid > 0) wprefix += s_wt[0];
    if (wid > 1) wprefix += s_wt[1];
    if (wid > 2) wprefix += s_wt[2];
    int excl = wprefix + incl - pair;      // count before bin 2*tid
    if (excl < need && excl + pair >= need) {
        if (excl + h0 >= need) { *s_out_bin = 2 * tid;     *s_out_c = excl; }
        else                   { *s_out_bin = 2 * tid + 1; *s_out_c = excl + h0; }
    }
    __syncthreads();
}

// ---------------------------------------------------------------------------
// Kernel 2: per-query kNN select (exact, radix-histogram) + weighted max/mean
// aggregation + output GEMM + tanh. One block (128 threads) per query vertex.
// ---------------------------------------------------------------------------
__global__ void __launch_bounds__(TPB) grav_kernel(
    const float* __restrict__ x,
    const float* __restrict__ Wo, const float* __restrict__ bo,
    float* __restrict__ out)
{
    const int v    = blockIdx.x;       // vertex within batch
    const int b    = blockIdx.y;       // batch
    const int tid  = threadIdx.x;
    const int lane = tid & 31;
    const int base = b * VV;

    __shared__ float s_d2[VV];                 // 16 KB
    __shared__ unsigned s_hist[256];
    __shared__ float s_xq[FF];
    __shared__ int   s_nidx[KN + 1];
    __shared__ float s_nd2[KN + 1];
    __shared__ float s_nw[KN + 1];
    __shared__ float s_coll[128];              // [max(64) | mean(64)]
    __shared__ float s_mx2[64], s_sm2[64], s_gemm[64];
    __shared__ unsigned long long s_bnd[BND_MAX];
    __shared__ unsigned long long s_red[4];
    __shared__ unsigned long long s_win;
    __shared__ int s_cdef, s_cbnd, s_estar, s_bprefix, s_c;

    const float4* cb = reinterpret_cast<const float4*>(g_coords) + base;
    const float4 cq = cb[v];

    if (tid < FF) s_xq[tid] = x[(base + v) * FF + tid];
    s_hist[tid] = 0u;
    s_hist[tid + 128] = 0u;
    __syncthreads();

    // ---- Pass 1: distances + level-1 histogram on exponent byte.
    //      Warp-aggregated (match_any) atomics: conflict degree <= #warps. ----
    for (int i = tid; i < VV; i += TPB) {
        float4 cu = cb[i];
        float dx = cq.x - cu.x, dy = cq.y - cu.y;
        float dz = cq.z - cu.z, dw = cq.w - cu.w;
        float d2 = fmaf(dx, dx, fmaf(dy, dy, fmaf(dz, dz, dw * dw)));
        unsigned key;
        if (i == v) {
            s_d2[i] = CUDART_INF_F;            // exclude self
            key = 0x1FFu;                       // sentinel, never counted
        } else {
            s_d2[i] = d2;
            key = __float_as_uint(d2) >> 23;
        }
        unsigned peers = __match_any_sync(0xffffffffu, key);
        if (key != 0x1FFu && lane == (__ffs(peers) - 1))
            atomicAdd(&s_hist[key], (unsigned)__popc(peers));
    }
    __syncthreads();

    scan_select_256(s_hist, KN, tid, &s_estar, &s_c);
    const int estar = s_estar;
    const int c1 = s_c;

    // ---- Pass 2: level-2 histogram on top-8 mantissa bits within estar ----
    s_hist[tid] = 0u;
    s_hist[tid + 128] = 0u;
    __syncthreads();
    for (int i = tid; i < VV; i += TPB) {
        unsigned u = __float_as_uint(s_d2[i]);
        unsigned key = ((int)(u >> 23) == estar) ? ((u >> 15) & 0xFFu) : 0x1FFu;
        unsigned peers = __match_any_sync(0xffffffffu, key);
        if (key != 0x1FFu && lane == (__ffs(peers) - 1))
            atomicAdd(&s_hist[key], (unsigned)__popc(peers));
    }
    __syncthreads();

    scan_select_256(s_hist, KN - c1, tid, &s_bprefix, &s_c);
    if (tid == 0) {
        s_bprefix = (estar << 8) | s_bprefix;
        s_c += c1;
        s_cdef = 0; s_cbnd = 0;
    }
    __syncthreads();
    const int bprefix = s_bprefix;
    const int c = s_c;                          // definite count (< 39)

    // ---- Pass 3: gather definite + boundary candidates ----
    for (int i = tid; i < VV; i += TPB) {
        unsigned u = __float_as_uint(s_d2[i]);
        int p = (int)(u >> 15);                 // 17-bit order-preserving prefix
        if (p < bprefix) {
            int pos = atomicAdd(&s_cdef, 1);
            s_nidx[pos] = i;
            s_nd2[pos] = s_d2[i];
        } else if (p == bprefix) {
            int pos = atomicAdd(&s_cbnd, 1);
            if (pos < BND_MAX)
                s_bnd[pos] = ((unsigned long long)u << 32) | (unsigned)i;
        }
    }
    __syncthreads();

    const int m = s_cbnd;
    const int r = KN - c;                       // boundary picks needed (>=1)

    if (m <= BND_MAX) {
        // Extract r smallest by (d2, idx) from the small boundary list.
        for (int j = 0; j < r; ++j) {
            unsigned long long lk = (tid < m) ? s_bnd[tid]
                                              : 0xFFFFFFFFFFFFFFFFULL;
#pragma unroll
            for (int o = 16; o > 0; o >>= 1) {
                unsigned long long oth = __shfl_down_sync(0xffffffffu, lk, o);
                lk = (oth < lk) ? oth : lk;
            }
            if (lane == 0) s_red[tid >> 5] = lk;
            __syncthreads();
            if (tid == 0) {
                unsigned long long w0 = s_red[0];
                if (s_red[1] < w0) w0 = s_red[1];
                if (s_red[2] < w0) w0 = s_red[2];
                if (s_red[3] < w0) w0 = s_red[3];
                s_win = w0;
                s_nidx[c + j] = (int)(w0 & 0xFFFFFFFFULL);
                s_nd2[c + j]  = __uint_as_float((unsigned)(w0 >> 32));
            }
            __syncthreads();
            if (tid < m && s_bnd[tid] == s_win)
                s_bnd[tid] = 0xFFFFFFFFFFFFFFFFULL;
            __syncthreads();
        }
    } else {
        // Degenerate fallback (massive tie bin): exact extraction over array.
        for (int j = 0; j < r; ++j) {
            unsigned long long lk = 0xFFFFFFFFFFFFFFFFULL;
            for (int i = tid; i < VV; i += TPB) {
                unsigned u = __float_as_uint(s_d2[i]);
                if ((int)(u >> 15) == bprefix) {
                    unsigned long long key =
                        ((unsigned long long)u << 32) | (unsigned)i;
                    if (key < lk) lk = key;
                }
            }
#pragma unroll
            for (int o = 16; o > 0; o >>= 1) {
                unsigned long long oth = __shfl_down_sync(0xffffffffu, lk, o);
                lk = (oth < lk) ? oth : lk;
            }
            if (lane == 0) s_red[tid >> 5] = lk;
            __syncthreads();
            if (tid == 0) {
                unsigned long long w0 = s_red[0];
                if (s_red[1] < w0) w0 = s_red[1];
                if (s_red[2] < w0) w0 = s_red[2];
                if (s_red[3] < w0) w0 = s_red[3];
                s_win = w0;
                int widx = (int)(w0 & 0xFFFFFFFFULL);
                s_nidx[c + j] = widx;
                s_nd2[c + j]  = __uint_as_float((unsigned)(w0 >> 32));
                s_d2[widx] = CUDART_INF_F;      // mark consumed
            }
            __syncthreads();
        }
    }

    // ---- Weights ----
    if (tid < KN)
        s_nw[tid] = expf(-10.0f * fabsf(s_nd2[tid]));
    __syncthreads();

    // ---- Weighted neighbour aggregation: max + mean over 39, all 128 thr ----
    {
        const float* fb = g_feats + (size_t)base * FF;
        const int f = tid & 63;
        const int half = tid >> 6;
        const int j0 = half ? 20 : 0;
        const int j1 = half ? KN : 20;
        float mx = -CUDART_INF_F;
        float sm = 0.0f;
        for (int j = j0; j < j1; ++j) {
            float val = fb[s_nidx[j] * FF + f] * s_nw[j];
            mx = fmaxf(mx, val);
            sm += val;
        }
        if (half) { s_mx2[f] = mx; s_sm2[f] = sm; }
        __syncthreads();
        if (!half) {
            mx = fmaxf(mx, s_mx2[f]);
            sm += s_sm2[f];
            s_coll[f]      = mx;
            s_coll[FF + f] = sm * (1.0f / KN);
        }
        __syncthreads();
    }

    // ---- Output GEMM: [x | max | mean] (192) @ Wo (192x64) + bo, tanh.
    //      k-range split 96/96 across the two thread halves. ----
    {
        const int o = tid & 63;
        float acc = 0.0f;
        if (tid < 64) {
#pragma unroll
            for (int k = 0; k < FF; ++k)
                acc = fmaf(s_xq[k], Wo[k * OUTF + o], acc);
#pragma unroll
            for (int k = 0; k < 32; ++k)
                acc = fmaf(s_coll[k], Wo[(FF + k) * OUTF + o], acc);
        } else {
#pragma unroll
            for (int k = 32; k < 128; ++k)
                acc = fmaf(s_coll[k], Wo[(FF + k) * OUTF + o], acc);
            s_gemm[o] = acc;
        }
        __syncthreads();
        if (tid < 64)
            out[(base + v) * OUTF + o] = tanhf(acc + s_gemm[o] + bo[o]);
    }
}

// ---------------------------------------------------------------------------
extern "C" void kernel_launch(void* const* d_in, const int* in_sizes, int n_in,
                              void* d_out, int out_size)
{
    const float* x  = (const float*)d_in[0];
    const float* Wf = (const float*)d_in[1];
    const float* bf = (const float*)d_in[2];
    const float* Ws = (const float*)d_in[3];
    const float* bs = (const float*)d_in[4];
    const float* Wo = (const float*)d_in[5];
    const float* bo = (const float*)d_in[6];
    float* out = (float*)d_out;

    prep_kernel<<<BB * VV, 64>>>(x, Wf, bf, Ws, bs);

    dim3 grid(VV, BB);
    grav_kernel<<<grid, TPB>>>(x, Wo, bo, out);
}

// round 4
// speedup vs baseline: 1.3644x; 1.3644x over previous
#include <cuda_runtime.h>
#include <math_constants.h>

#define BB 4
#define VV 4096
#define FF 64
#define SS 4
#define KN 39            // neighbours kept (K_NEIGHBOURS=40 includes self)
#define OUTF 64
#define TPB 128
#define BND_MAX 64
#define NB 1024          // histogram bins
#define KBASE 1520       // (u>>19) offset: covers biased exponents 95..158

// Scratch (device globals; no allocation allowed)
__device__ float g_coords[BB * VV * 4];     // (b, v, 4) — float4-aligned rows
__device__ float g_feats[BB * VV * FF];     // (b, v, 64)

// ---------------------------------------------------------------------------
// Kernel 1: coords = x@Ws + bs, feats = x@Wf + bf
// ---------------------------------------------------------------------------
__global__ void __launch_bounds__(64) prep_kernel(
    const float* __restrict__ x,
    const float* __restrict__ Wf, const float* __restrict__ bf,
    const float* __restrict__ Ws, const float* __restrict__ bs)
{
    const int vtx = blockIdx.x;        // 0 .. B*V-1
    const int f   = threadIdx.x;       // 0 .. 63
    __shared__ float sx[FF];
    sx[f] = x[vtx * FF + f];
    __syncthreads();

    float acc = bf[f];
#pragma unroll
    for (int k = 0; k < FF; ++k)
        acc = fmaf(sx[k], Wf[k * FF + f], acc);
    g_feats[vtx * FF + f] = acc;

    if (f < SS) {
        float c = bs[f];
#pragma unroll
        for (int k = 0; k < FF; ++k)
            c = fmaf(sx[k], Ws[k * SS + f], c);
        g_coords[vtx * 4 + f] = c;
    }
}

__device__ __forceinline__ int d2_key(unsigned u)
{
    int p = (int)(u >> 19) - KBASE;
    p = max(p, 0);
    return min(p, NB - 1);
}

// ---------------------------------------------------------------------------
// Kernel 2: per-query kNN select (single-level radix histogram) + weighted
// max/mean aggregation + output GEMM + tanh. One block per query vertex.
// ---------------------------------------------------------------------------
__global__ void __launch_bounds__(TPB) grav_kernel(
    const float* __restrict__ x,
    const float* __restrict__ Wo, const float* __restrict__ bo,
    float* __restrict__ out)
{
    const int v    = blockIdx.x;       // vertex within batch
    const int b    = blockIdx.y;       // batch
    const int tid  = threadIdx.x;
    const int lane = tid & 31;
    const int base = b * VV;

    __shared__ float4 s_d2v[VV / 4];           // 16 KB (float4 view of d2)
    __shared__ unsigned s_hist[NB];            // 4 KB
    __shared__ float s_xq[FF];
    __shared__ int   s_nidx[KN + 1];
    __shared__ float s_nd2[KN + 1];
    __shared__ float s_nw[KN + 1];
    __shared__ float s_coll[128];              // [max(64) | mean(64)]
    __shared__ float s_mx2[64], s_sm2[64], s_gemm[64];
    __shared__ unsigned long long s_bnd[BND_MAX];
    __shared__ unsigned long long s_red[4];
    __shared__ unsigned long long s_win;
    __shared__ int s_cdef, s_cbnd, s_bkey, s_c;
    __shared__ int s_wt[4];

    float* s_d2 = reinterpret_cast<float*>(s_d2v);

    const float4* cb = reinterpret_cast<const float4*>(g_coords) + base;
    const float4 cq = cb[v];

    if (tid < FF) s_xq[tid] = x[(base + v) * FF + tid];
    {
        uint4* h4 = reinterpret_cast<uint4*>(s_hist);
#pragma unroll
        for (int j = 0; j < NB / 4 / TPB; ++j)
            h4[j * TPB + tid] = make_uint4(0u, 0u, 0u, 0u);
    }
    if (tid == 0) { s_cdef = 0; s_cbnd = 0; }
    __syncthreads();

    // ---- Pass 1: distances + 1024-bin histogram (fused, single pass) ----
    for (int i = tid; i < VV; i += TPB) {
        float4 cu = cb[i];
        float dx = cq.x - cu.x, dy = cq.y - cu.y;
        float dz = cq.z - cu.z, dw = cq.w - cu.w;
        float d2 = fmaf(dx, dx, fmaf(dy, dy, fmaf(dz, dz, dw * dw)));
        if (i == v) d2 = CUDART_INF_F;          // exclude self
        s_d2[i] = d2;
        if (i != v)
            atomicAdd(&s_hist[d2_key(__float_as_uint(d2))], 1u);
    }
    __syncthreads();

    // ---- Parallel scan over 1024 bins: find crossing bin + prefix count ----
    {
        unsigned h[8];
        uint4 a = reinterpret_cast<uint4*>(s_hist)[2 * tid];
        uint4 c4 = reinterpret_cast<uint4*>(s_hist)[2 * tid + 1];
        h[0] = a.x; h[1] = a.y; h[2] = a.z; h[3] = a.w;
        h[4] = c4.x; h[5] = c4.y; h[6] = c4.z; h[7] = c4.w;
        int lsum = 0;
#pragma unroll
        for (int j = 0; j < 8; ++j) lsum += (int)h[j];
        int incl = lsum;
#pragma unroll
        for (int o = 1; o < 32; o <<= 1) {
            int n = __shfl_up_sync(0xffffffffu, incl, o);
            if (lane >= o) incl += n;
        }
        if (lane == 31) s_wt[tid >> 5] = incl;
        __syncthreads();
        int wprefix = 0;
        const int wid = tid >> 5;
        if (wid > 0) wprefix += s_wt[0];
        if (wid > 1) wprefix += s_wt[1];
        if (wid > 2) wprefix += s_wt[2];
        int excl = wprefix + incl - lsum;       // count before bin tid*8
        if (excl < KN && excl + lsum >= KN) {
            int cum = excl;
#pragma unroll
            for (int j = 0; j < 8; ++j) {
                if (cum + (int)h[j] >= KN) { s_bkey = tid * 8 + j; s_c = cum; break; }
                cum += (int)h[j];
            }
        }
        __syncthreads();
    }
    const int bkey = s_bkey;
    const int c = s_c;                          // definite count (< 39)

    // ---- Pass 2: gather definite + boundary candidates (vectorized) ----
    for (int it = 0; it < VV / 4 / TPB; ++it) {
        int i4 = it * TPB + tid;
        float4 d4 = s_d2v[i4];
        int ib = i4 * 4;
#pragma unroll
        for (int e = 0; e < 4; ++e) {
            float dv = (e == 0) ? d4.x : (e == 1) ? d4.y : (e == 2) ? d4.z : d4.w;
            int i = ib + e;
            unsigned u = __float_as_uint(dv);
            int p = d2_key(u);
            if (p <= bkey && i != v) {
                if (p < bkey) {
                    int pos = atomicAdd(&s_cdef, 1);
                    s_nidx[pos] = i;
                    s_nd2[pos] = dv;
                } else {
                    int pos = atomicAdd(&s_cbnd, 1);
                    if (pos < BND_MAX)
                        s_bnd[pos] = ((unsigned long long)u << 32) | (unsigned)i;
                }
            }
        }
    }
    __syncthreads();

    const int m = s_cbnd;
    const int r = KN - c;                       // boundary picks needed (>=1)

    if (m <= BND_MAX) {
        // Extract r smallest by (d2, idx) from the small boundary list.
        for (int j = 0; j < r; ++j) {
            unsigned long long lk = (tid < m) ? s_bnd[tid]
                                              : 0xFFFFFFFFFFFFFFFFULL;
#pragma unroll
            for (int o = 16; o > 0; o >>= 1) {
                unsigned long long oth = __shfl_down_sync(0xffffffffu, lk, o);
                lk = (oth < lk) ? oth : lk;
            }
            if (lane == 0) s_red[tid >> 5] = lk;
            __syncthreads();
            if (tid == 0) {
                unsigned long long w0 = s_red[0];
                if (s_red[1] < w0) w0 = s_red[1];
                if (s_red[2] < w0) w0 = s_red[2];
                if (s_red[3] < w0) w0 = s_red[3];
                s_win = w0;
                s_nidx[c + j] = (int)(w0 & 0xFFFFFFFFULL);
                s_nd2[c + j]  = __uint_as_float((unsigned)(w0 >> 32));
            }
            __syncthreads();
            if (tid < m && s_bnd[tid] == s_win)
                s_bnd[tid] = 0xFFFFFFFFFFFFFFFFULL;
            __syncthreads();
        }
    } else {
        // Degenerate fallback (massive tie bin): exact extraction over array.
        for (int j = 0; j < r; ++j) {
            unsigned long long lk = 0xFFFFFFFFFFFFFFFFULL;
            for (int i = tid; i < VV; i += TPB) {
                unsigned u = __float_as_uint(s_d2[i]);
                if (d2_key(u) == bkey && i != v) {
                    unsigned long long key =
                        ((unsigned long long)u << 32) | (unsigned)i;
                    if (key < lk) lk = key;
                }
            }
#pragma unroll
            for (int o = 16; o > 0; o >>= 1) {
                unsigned long long oth = __shfl_down_sync(0xffffffffu, lk, o);
                lk = (oth < lk) ? oth : lk;
            }
            if (lane == 0) s_red[tid >> 5] = lk;
            __syncthreads();
            if (tid == 0) {
                unsigned long long w0 = s_red[0];
                if (s_red[1] < w0) w0 = s_red[1];
                if (s_red[2] < w0) w0 = s_red[2];
                if (s_red[3] < w0) w0 = s_red[3];
                s_win = w0;
                int widx = (int)(w0 & 0xFFFFFFFFULL);
                s_nidx[c + j] = widx;
                s_nd2[c + j]  = __uint_as_float((unsigned)(w0 >> 32));
                s_d2[widx] = CUDART_INF_F;      // mark consumed
            }
            __syncthreads();
        }
    }

    // ---- Weights ----
    if (tid < KN)
        s_nw[tid] = expf(-10.0f * fabsf(s_nd2[tid]));
    __syncthreads();

    // ---- Weighted neighbour aggregation: max + mean over 39, all 128 thr ----
    {
        const float* fb = g_feats + (size_t)base * FF;
        const int f = tid & 63;
        const int half = tid >> 6;
        const int j0 = half ? 20 : 0;
        const int j1 = half ? KN : 20;
        float mx = -CUDART_INF_F;
        float sm = 0.0f;
        for (int j = j0; j < j1; ++j) {
            float val = fb[s_nidx[j] * FF + f] * s_nw[j];
            mx = fmaxf(mx, val);
            sm += val;
        }
        if (half) { s_mx2[f] = mx; s_sm2[f] = sm; }
        __syncthreads();
        if (!half) {
            mx = fmaxf(mx, s_mx2[f]);
            sm += s_sm2[f];
            s_coll[f]      = mx;
            s_coll[FF + f] = sm * (1.0f / KN);
        }
        __syncthreads();
    }

    // ---- Output GEMM: [x | max | mean] (192) @ Wo (192x64) + bo, tanh.
    //      k-range split 96/96 across the two thread halves. ----
    {
        const int o = tid & 63;
        float acc = 0.0f;
        if (tid < 64) {
#pragma unroll
            for (int k = 0; k < FF; ++k)
                acc = fmaf(s_xq[k], Wo[k * OUTF + o], acc);
#pragma unroll
            for (int k = 0; k < 32; ++k)
                acc = fmaf(s_coll[k], Wo[(FF + k) * OUTF + o], acc);
        } else {
#pragma unroll
            for (int k = 32; k < 128; ++k)
                acc = fmaf(s_coll[k], Wo[(FF + k) * OUTF + o], acc);
            s_gemm[o] = acc;
        }
        __syncthreads();
        if (tid < 64)
            out[(base + v) * OUTF + o] = tanhf(acc + s_gemm[o] + bo[o]);
    }
}

// ---------------------------------------------------------------------------
extern "C" void kernel_launch(void* const* d_in, const int* in_sizes, int n_in,
                              void* d_out, int out_size)
{
    const float* x  = (const float*)d_in[0];
    const float* Wf = (const float*)d_in[1];
    const float* bf = (const float*)d_in[2];
    const float* Ws = (const float*)d_in[3];
    const float* bs = (const float*)d_in[4];
    const float* Wo = (const float*)d_in[5];
    const float* bo = (const float*)d_in[6];
    float* out = (float*)d_out;

    prep_kernel<<<BB * VV, 64>>>(x, Wf, bf, Ws, bs);

    dim3 grid(VV, BB);
    grav_kernel<<<grid, TPB>>>(x, Wo, bo, out);
}